// round 2
// baseline (speedup 1.0000x reference)
#include <cuda_runtime.h>
#include <cuda_bf16.h>

// PeriodicConvOp == parity-scrambled 3x3 conv.
// x: [8,4,512,512] f32, weight: [32,36] f32, out: [8,8,512,512] f32.
//
// For flat channel n in [0,32): g = n>>3 (gy=g>>1, gx=g&1), o = n&7:
//   conv[n](h,w) = sum_{cin,ky,kx} W[(g*8+o)*36 + cin*9+ky*3+kx]
//                  * x[b,cin, 2h+gy+ky-1, 2w+gx+kx-1]
//   out[b, n>>2, 2h + ((n>>1)&1), 2w + (n&1)] = conv[n](h,w)
//
// Thread layout (512 thr): m = tid&3 (owns o pair {2m,2m+1} -> j=0/1 pair,
// co = 2g+(m>>1), out row parity i = m&1), tcx = (tid>>2)&7 (superpixel pair
// x = {2tcx, 2tcx+1}), ty = tid>>5 (superpixel row). Tile: 16x16 superpixels
// = 32x32 output px per block.

#define PITCH 34            // input tile row length (duplicated float2 elems)

__device__ __forceinline__ void ffma2(unsigned long long& d,
                                      unsigned long long a,
                                      unsigned long long b) {
    asm("fma.rn.f32x2 %0, %1, %2, %0;" : "+l"(d) : "l"(a), "l"(b));
}

__global__ __launch_bounds__(512, 1)
void pconv_kernel(const float* __restrict__ x, const float* __restrict__ wg,
                  float* __restrict__ out) {
    // input tile, each element duplicated {v,v} for packed-broadcast LDS.128
    __shared__ __align__(16) float2 s_in[4 * 34 * PITCH];
    // weights: s_w[((tap*4 + m)*4 + g)*2 + e] = W[(g*8 + 2m + e)*36 + tap]
    __shared__ __align__(16) float s_w[1152];

    const int tid = threadIdx.x;
    const int b   = blockIdx.z;
    const int h0  = blockIdx.y * 16;      // superpixel row base
    const int w0  = blockIdx.x * 16;      // superpixel col base
    const int py0 = 2 * h0 - 1;           // pixel row of tile row 0
    const int px0 = 2 * w0 - 1;

    // ---- stage weights (transposed/interleaved) ----
    for (int d = tid; d < 1152; d += 512) {
        int e = d & 1, g = (d >> 1) & 3, m = (d >> 3) & 3, tap = d >> 5;
        s_w[d] = wg[(g * 8 + 2 * m + e) * 36 + tap];
    }

    // ---- stage input tile, duplicated, zero-padded at borders ----
    const float* xb = x + (size_t)b * 4 * 512 * 512;
    for (int e = tid; e < 4 * 34 * 34; e += 512) {
        int cin = e / (34 * 34);
        int rem = e - cin * (34 * 34);
        int r = rem / 34;
        int c = rem - r * 34;
        int gr = py0 + r, gc = px0 + c;
        float v = 0.f;
        if ((unsigned)gr < 512u && (unsigned)gc < 512u)
            v = xb[(cin * 512 + gr) * 512 + gc];
        s_in[(cin * 34 + r) * PITCH + c] = make_float2(v, v);
    }
    __syncthreads();

    const int m   = tid & 3;
    const int tcx = (tid >> 2) & 7;
    const int ty  = tid >> 5;

    // acc[g][sp]: f32x2 = (out j=0, out j=1) for plane co=2g+(m>>1),
    // row 2*(h0+ty)+(m&1), superpixel x = w0 + 2*tcx + sp
    unsigned long long acc[4][2];
    #pragma unroll
    for (int g = 0; g < 4; g++) { acc[g][0] = 0ull; acc[g][1] = 0ull; }

    #pragma unroll
    for (int cin = 0; cin < 4; cin++) {
        // 4 rows x 6 cols of packed {v,v} inputs
        unsigned long long in[4][6];
        #pragma unroll
        for (int r = 0; r < 4; r++) {
            const float2* sp = &s_in[(cin * 34 + 2 * ty + r) * PITCH + 4 * tcx];
            const ulonglong2 a = *(const ulonglong2*)(sp);
            const ulonglong2 q = *(const ulonglong2*)(sp + 2);
            const ulonglong2 c2 = *(const ulonglong2*)(sp + 4);
            in[r][0] = a.x;  in[r][1] = a.y;
            in[r][2] = q.x;  in[r][3] = q.y;
            in[r][4] = c2.x; in[r][5] = c2.y;
        }
        #pragma unroll
        for (int ky = 0; ky < 3; ky++) {
            #pragma unroll
            for (int kx = 0; kx < 3; kx++) {
                const int tap = cin * 9 + ky * 3 + kx;
                // weight pairs for all 4 g at this (tap, m): 2x LDS.128
                const float* wb = &s_w[tap * 32 + m * 8];
                const ulonglong2 w01 = *(const ulonglong2*)(wb);
                const ulonglong2 w23 = *(const ulonglong2*)(wb + 4);
                unsigned long long w4[4] = { w01.x, w01.y, w23.x, w23.y };
                #pragma unroll
                for (int g = 0; g < 4; g++) {
                    const int gy = g >> 1, gx = g & 1;
                    ffma2(acc[g][0], w4[g], in[gy + ky][gx + kx]);
                    ffma2(acc[g][1], w4[g], in[gy + ky][2 + gx + kx]);
                }
            }
        }
    }

    // ---- coalesced stores: one STG.128 per g covers 4 consecutive px ----
    float* ob = out + (size_t)b * 8 * 512 * 512;
    const int row = 2 * (h0 + ty) + (m & 1);
    const int colbase = 2 * w0 + 4 * tcx;
    #pragma unroll
    for (int g = 0; g < 4; g++) {
        const int co = 2 * g + (m >> 1);
        ulonglong2 v; v.x = acc[g][0]; v.y = acc[g][1];
        *(ulonglong2*)(ob + ((size_t)co * 512 + row) * 512 + colbase) = v;
    }
}

extern "C" void kernel_launch(void* const* d_in, const int* in_sizes, int n_in,
                              void* d_out, int out_size) {
    const float* x = (const float*)d_in[0];   // [8,4,512,512]
    const float* w = (const float*)d_in[1];   // [32,36,1,1]
    float* out = (float*)d_out;               // [8,8,512,512]
    dim3 grid(16, 16, 8);                     // 2048 blocks
    pconv_kernel<<<grid, 512>>>(x, w, out);
}

// round 3
// speedup vs baseline: 1.2920x; 1.2920x over previous
#include <cuda_runtime.h>
#include <cuda_bf16.h>

// PeriodicConvOp == parity-scrambled 3x3 conv.
// x: [8,4,512,512] f32, weight: [32,36] f32, out: [8,8,512,512] f32.
//
// For flat channel n in [0,32): g = n>>3 (gy=g>>1, gx=g&1), o = n&7:
//   conv[n](h,w) = sum_{cin,ky,kx} W[(g*8+o)*36 + cin*9+ky*3+kx]
//                  * x[b,cin, 2h+gy+ky-1, 2w+gx+kx-1]
//   out[b, n>>2, 2h + ((n>>1)&1), 2w + (n&1)] = conv[n](h,w)
//
// 256 threads: m = tid&3 (o-pair {2m,2m+1} -> j=0/1 f32x2 lanes),
// tcx = (tid>>2)&3 (4 superpixels: 4*tcx..4*tcx+3), ty = tid>>4.
// Tile: 16x16 superpixels (32x32 out px). 4 sp/thread => weight reuse 4x.

#define PITCH 34   // input tile row length in (duplicated) float2 elements

__device__ __forceinline__ void ffma2(unsigned long long& d,
                                      unsigned long long a,
                                      unsigned long long b) {
    asm("fma.rn.f32x2 %0, %1, %2, %0;" : "+l"(d) : "l"(a), "l"(b));
}

__global__ __launch_bounds__(256, 2)
void pconv_kernel(const float* __restrict__ x, const float* __restrict__ wg,
                  float* __restrict__ out) {
    // input tile, each element duplicated {v,v} for packed-broadcast LDS.128
    __shared__ __align__(16) float2 s_in[4 * 34 * PITCH];
    // weights: s_w[((tap*4 + m)*4 + g)*2 + e] = W[(g*8 + 2m + e)*36 + tap]
    __shared__ __align__(16) float s_w[1152];

    const int tid = threadIdx.x;
    const int b   = blockIdx.z;
    const int h0  = blockIdx.y * 16;      // superpixel row base
    const int w0  = blockIdx.x * 16;      // superpixel col base
    const int py0 = 2 * h0 - 1;           // pixel row of tile row 0
    const int px0 = 2 * w0 - 1;

    // ---- stage weights (transposed/interleaved) ----
    for (int d = tid; d < 1152; d += 256) {
        int e = d & 1, g = (d >> 1) & 3, m = (d >> 3) & 3, tap = d >> 5;
        s_w[d] = wg[(g * 8 + 2 * m + e) * 36 + tap];
    }

    // ---- stage input tile, duplicated, zero-padded at borders ----
    const float* xb = x + (size_t)b * 4 * 512 * 512;
    for (int e = tid; e < 4 * 34 * 34; e += 256) {
        int cin = e / (34 * 34);
        int rem = e - cin * (34 * 34);
        int r = rem / 34;
        int c = rem - r * 34;
        int gr = py0 + r, gc = px0 + c;
        float v = 0.f;
        if ((unsigned)gr < 512u && (unsigned)gc < 512u)
            v = xb[(cin * 512 + gr) * 512 + gc];
        s_in[(cin * 34 + r) * PITCH + c] = make_float2(v, v);
    }
    __syncthreads();

    const int m   = tid & 3;
    const int tcx = (tid >> 2) & 3;
    const int ty  = tid >> 4;

    // acc[g][sp]: f32x2 = (out j=0, out j=1) for plane co = 2g + (m>>1),
    // out row 2*(h0+ty) + (m&1), superpixel x = w0 + 4*tcx + sp
    unsigned long long acc[4][4];
    #pragma unroll
    for (int g = 0; g < 4; g++)
        #pragma unroll
        for (int sp = 0; sp < 4; sp++)
            acc[g][sp] = 0ull;

    #pragma unroll
    for (int cin = 0; cin < 4; cin++) {
        const float2* rowbase = &s_in[(cin * 34 + 2 * ty) * PITCH + 8 * tcx];
        // rolling 2-row window of 10 packed {v,v} values each
        unsigned long long rA[5], rB[5];
        {
            const ulonglong2 a0 = *(const ulonglong2*)(rowbase);
            const ulonglong2 a1 = *(const ulonglong2*)(rowbase + 2);
            rA[0] = a0.x; rA[1] = a0.y; rA[2] = a1.x; rA[3] = a1.y;
            rA[4] = *(const unsigned long long*)(rowbase + 4);
            const float2* rb = rowbase + PITCH;
            const ulonglong2 b0 = *(const ulonglong2*)(rb);
            const ulonglong2 b1 = *(const ulonglong2*)(rb + 2);
            rB[0] = b0.x; rB[1] = b0.y; rB[2] = b1.x; rB[3] = b1.y;
            rB[4] = *(const unsigned long long*)(rb + 4);
        }
        // NOTE rA[i] covers pair positions {2i, 2i+1}; we index scalar pos p
        // via a flat copy view below.
        unsigned long long winA[10], winB[10];
        #pragma unroll
        for (int ky = 0; ky < 3; ky++) {
            // materialize scalar-position views (registers, renamed per ky)
            // position p corresponds to packed element rowbase[p]
            // (each smem float2 is one position; loads above fetched 10)
            #pragma unroll
            for (int i = 0; i < 5; i++) { winA[2*i] = rA[i]; winB[2*i] = rB[i]; }
            // odd positions: reload as unaligned u64 is illegal; instead
            // fetch odd-offset pairs directly from smem (LDS.64, cheap: 8B)
            // -- but that adds traffic. Better: positions are float2 elems,
            // so rA[i] IS position... (see loader below)
            (void)winA; (void)winB;
            ky = ky; // placeholder to keep structure clear
            break;
        }
        // ---- actual compute: load each row as 10 individual positions ----
        // (rA/rB trick above only covers even positions; do it properly:)
        unsigned long long row0[10], row1[10];
        #pragma unroll
        for (int p = 0; p < 10; p += 2) {
            const ulonglong2 v0 = *(const ulonglong2*)(rowbase + p);
            row0[p] = v0.x; row0[p + 1] = v0.y;
            const ulonglong2 v1 = *(const ulonglong2*)(rowbase + PITCH + p);
            row1[p] = v1.x; row1[p + 1] = v1.y;
        }
        #pragma unroll
        for (int ky = 0; ky < 3; ky++) {
            #pragma unroll
            for (int kx = 0; kx < 3; kx++) {
                const int tap = cin * 9 + ky * 3 + kx;
                const float* wb = &s_w[tap * 32 + m * 8];
                const ulonglong2 w01 = *(const ulonglong2*)(wb);
                const ulonglong2 w23 = *(const ulonglong2*)(wb + 4);
                unsigned long long w4[4] = { w01.x, w01.y, w23.x, w23.y };
                #pragma unroll
                for (int g = 0; g < 4; g++) {
                    const int gx = g & 1;
                    const unsigned long long* rw = ((g >> 1) == 0) ? row0 : row1;
                    #pragma unroll
                    for (int sp = 0; sp < 4; sp++)
                        ffma2(acc[g][sp], w4[g], rw[2 * sp + gx + kx]);
                }
            }
            // roll: row0 <- row1, row1 <- next smem row
            if (ky < 2) {
                #pragma unroll
                for (int p = 0; p < 10; p++) row0[p] = row1[p];
                const float2* rn = rowbase + (ky + 2) * PITCH;
                #pragma unroll
                for (int p = 0; p < 10; p += 2) {
                    const ulonglong2 v = *(const ulonglong2*)(rn + p);
                    row1[p] = v.x; row1[p + 1] = v.y;
                }
            }
        }
    }

    // ---- coalesced stores: per g, 8 consecutive px = 2x STG.128 ----
    float* ob = out + (size_t)b * 8 * 512 * 512;
    const int row = 2 * (h0 + ty) + (m & 1);
    const int colbase = 2 * w0 + 8 * tcx;
    #pragma unroll
    for (int g = 0; g < 4; g++) {
        const int co = 2 * g + (m >> 1);
        float* orow = ob + ((size_t)co * 512 + row) * 512 + colbase;
        ulonglong2 v0; v0.x = acc[g][0]; v0.y = acc[g][1];
        ulonglong2 v1; v1.x = acc[g][2]; v1.y = acc[g][3];
        *(ulonglong2*)(orow) = v0;
        *(ulonglong2*)(orow + 4) = v1;
    }
}

extern "C" void kernel_launch(void* const* d_in, const int* in_sizes, int n_in,
                              void* d_out, int out_size) {
    const float* x = (const float*)d_in[0];   // [8,4,512,512]
    const float* w = (const float*)d_in[1];   // [32,36,1,1]
    float* out = (float*)d_out;               // [8,8,512,512]
    dim3 grid(16, 16, 8);                     // 2048 blocks, 256 thr
    pconv_kernel<<<grid, 256>>>(x, w, out);
}

// round 6
// speedup vs baseline: 1.6276x; 1.2598x over previous
#include <cuda_runtime.h>
#include <cuda_bf16.h>

// PeriodicConvOp == parity-scrambled 3x3 conv.
// x: [8,4,512,512] f32, weight: [32,36] f32, out: [8,8,512,512] f32.
//
// For flat channel n in [0,32): g = n>>3 (gy=g>>1, gx=g&1), o = n&7:
//   conv[n](h,w) = sum_{cin,ky,kx} W[(g*8+o)*36 + cin*9+ky*3+kx]
//                  * x[b,cin, 2h+gy+ky-1, 2w+gx+kx-1]
//   out[b, n>>2, 2h + ((n>>1)&1), 2w + (n&1)] = conv[n](h,w)
//
// 256 threads: m = tid&3 (o-pair {2m,2m+1} -> j=0/1 f32x2 lanes),
// tcx = (tid>>2)&3 (4 superpixels), ty = tid>>4 (0..15).
// Tile: 16x16 superpixels (32x32 out px) per block.
//
// Row-major schedule: smem row r of the 4-row window feeds (gy, ky=r-gy)
// for gy in {0,1}; iterating r keeps exactly ONE row array live (20 regs).

#define PITCH 34   // input tile row length in (duplicated) float2 elements

__device__ __forceinline__ void ffma2(unsigned long long& d,
                                      unsigned long long a,
                                      unsigned long long b) {
    asm("fma.rn.f32x2 %0, %1, %2, %0;" : "+l"(d) : "l"(a), "l"(b));
}

// load 10 consecutive packed {v,v} positions (5x LDS.128)
__device__ __forceinline__ void ldrow(unsigned long long* r, const float2* p) {
    const ulonglong2 a = *(const ulonglong2*)(p);
    const ulonglong2 b = *(const ulonglong2*)(p + 2);
    const ulonglong2 c = *(const ulonglong2*)(p + 4);
    const ulonglong2 d = *(const ulonglong2*)(p + 6);
    const ulonglong2 e = *(const ulonglong2*)(p + 8);
    r[0] = a.x; r[1] = a.y; r[2] = b.x; r[3] = b.y; r[4] = c.x;
    r[5] = c.y; r[6] = d.x; r[7] = d.y; r[8] = e.x; r[9] = e.y;
}

__global__ __launch_bounds__(256, 3)
void pconv_kernel(const float* __restrict__ x, const float* __restrict__ wg,
                  float* __restrict__ out) {
    // input tile, each element duplicated {v,v} for packed-broadcast LDS.128
    __shared__ __align__(16) float2 s_in[4 * 34 * PITCH];
    // weights: s_w[((tap*4 + m)*4 + g)*2 + e] = W[(g*8 + 2m + e)*36 + tap]
    __shared__ __align__(16) float s_w[1152];

    const int tid = threadIdx.x;
    const int b   = blockIdx.z;
    const int h0  = blockIdx.y * 16;      // superpixel row base
    const int w0  = blockIdx.x * 16;      // superpixel col base
    const int py0 = 2 * h0 - 1;           // pixel row of tile row 0
    const int px0 = 2 * w0 - 1;

    // ---- stage weights (transposed/interleaved) ----
    for (int d = tid; d < 1152; d += 256) {
        int e = d & 1, g = (d >> 1) & 3, m = (d >> 3) & 3, tap = d >> 5;
        s_w[d] = wg[(g * 8 + 2 * m + e) * 36 + tap];
    }

    // ---- stage input tile, duplicated, zero-padded at borders ----
    const float* xb = x + (size_t)b * 4 * 512 * 512;
    for (int e = tid; e < 4 * 34 * 34; e += 256) {
        int cin = e / (34 * 34);
        int rem = e - cin * (34 * 34);
        int r = rem / 34;
        int c = rem - r * 34;
        int gr = py0 + r, gc = px0 + c;
        float v = 0.f;
        if ((unsigned)gr < 512u && (unsigned)gc < 512u)
            v = xb[(cin * 512 + gr) * 512 + gc];
        s_in[(cin * 34 + r) * PITCH + c] = make_float2(v, v);
    }
    __syncthreads();

    const int m   = tid & 3;
    const int tcx = (tid >> 2) & 3;
    const int ty  = tid >> 4;

    const float* s_wm = s_w + m * 8;   // weight base for this thread's m

    // acc[g][sp]: f32x2 = (out j=0, out j=1) for plane co = 2g + (m>>1),
    // out row 2*(h0+ty) + (m&1), superpixel x = w0 + 4*tcx + sp
    unsigned long long acc[4][4];
    #pragma unroll
    for (int g = 0; g < 4; g++)
        #pragma unroll
        for (int sp = 0; sp < 4; sp++)
            acc[g][sp] = 0ull;

    // apply row `row` to group-half gy (g = 2*gy, 2*gy+1) at tap row ky
    #define APPLY(GY, KY, CIN, ROW)                                         \
    {                                                                       \
        _Pragma("unroll")                                                   \
        for (int kx = 0; kx < 3; kx++) {                                    \
            const float* wb = s_wm + ((CIN) * 9 + (KY) * 3 + kx) * 32       \
                              + (GY) * 4;                                   \
            const ulonglong2 wp = *(const ulonglong2*)(wb);                 \
            _Pragma("unroll")                                               \
            for (int sp = 0; sp < 4; sp++) {                                \
                ffma2(acc[2 * (GY) + 0][sp], wp.x, (ROW)[2 * sp + 0 + kx]); \
                ffma2(acc[2 * (GY) + 1][sp], wp.y, (ROW)[2 * sp + 1 + kx]); \
            }                                                               \
        }                                                                   \
    }

    #pragma unroll
    for (int cin = 0; cin < 4; cin++) {
        const float2* rowbase = &s_in[(cin * 34 + 2 * ty) * PITCH + 8 * tcx];
        unsigned long long row[10];

        ldrow(row, rowbase);                 // r = 0
        APPLY(0, 0, cin, row)                //   gy=0, ky=0
        ldrow(row, rowbase + PITCH);         // r = 1
        APPLY(0, 1, cin, row)                //   gy=0, ky=1
        APPLY(1, 0, cin, row)                //   gy=1, ky=0
        ldrow(row, rowbase + 2 * PITCH);     // r = 2
        APPLY(0, 2, cin, row)                //   gy=0, ky=2
        APPLY(1, 1, cin, row)                //   gy=1, ky=1
        ldrow(row, rowbase + 3 * PITCH);     // r = 3
        APPLY(1, 2, cin, row)                //   gy=1, ky=2
    }
    #undef APPLY

    // ---- coalesced stores: per g, 8 consecutive px = 2x STG.128 ----
    float* ob = out + (size_t)b * 8 * 512 * 512;
    const int row_y = 2 * (h0 + ty) + (m & 1);
    const int colbase = 2 * w0 + 8 * tcx;
    #pragma unroll
    for (int g = 0; g < 4; g++) {
        const int co = 2 * g + (m >> 1);
        float* orow = ob + ((size_t)co * 512 + row_y) * 512 + colbase;
        ulonglong2 v0; v0.x = acc[g][0]; v0.y = acc[g][1];
        ulonglong2 v1; v1.x = acc[g][2]; v1.y = acc[g][3];
        *(ulonglong2*)(orow) = v0;
        *(ulonglong2*)(orow + 4) = v1;
    }
}

extern "C" void kernel_launch(void* const* d_in, const int* in_sizes, int n_in,
                              void* d_out, int out_size) {
    const float* x = (const float*)d_in[0];   // [8,4,512,512]
    const float* w = (const float*)d_in[1];   // [32,36,1,1]
    float* out = (float*)d_out;               // [8,8,512,512]
    dim3 grid(16, 16, 8);                     // 2048 blocks, 256 thr
    pconv_kernel<<<grid, 256>>>(x, w, out);
}